// round 2
// baseline (speedup 1.0000x reference)
#include <cuda_runtime.h>
#include <math.h>

// Problem constants
#define BSZ   65536
#define SEQ   25
#define HID   64
#define ACT   4
#define TSTEP 16
#define BETA  0.95f
#define THRV  1.0f
#define ELIG_DECAY 0.95f
#define ELIG_C     (-0.002f)   // A_PLUS - A_MINUS = 0.008 - 0.01

// Global scratch for per-timestep spike sums (graph-safe: __device__ globals)
__device__ float g_s2sum[TSTEP * HID];   // sum over batch of s2 at each t
__device__ float g_s3sum[TSTEP * ACT];   // sum over batch of s3 at each t

// ---------------------------------------------------------------------------
// Kernel 0: zero the accumulators (must re-run every graph replay)
// ---------------------------------------------------------------------------
__global__ void snn_zero_sums() {
    int i = threadIdx.x;                 // 1024 threads
    if (i < TSTEP * HID) g_s2sum[i] = 0.0f;
    if (i < TSTEP * ACT) g_s3sum[i] = 0.0f;
}

// ---------------------------------------------------------------------------
// Kernel 1: main SNN simulation. One warp per batch row.
// Lane l owns hidden elements j0=2l, j1=2l+1 of m1 and m2.
// m3/acc (A=4) replicated across all lanes after butterfly reduce.
// ---------------------------------------------------------------------------
__global__ void __launch_bounds__(256) snn_main(
    const float* __restrict__ x,   // [B, 25]
    const float* __restrict__ W1,  // [64, 25]
    const float* __restrict__ b1,  // [64]
    const float* __restrict__ W2,  // [64, 64]
    const float* __restrict__ b2,  // [64]
    const float* __restrict__ W3,  // [4, 64]
    const float* __restrict__ b3,  // [4]
    float* __restrict__ out)       // probs at [0, B*4)
{
    __shared__ float2 w1t[SEQ][HID / 2];   // w1t[k][l] = (W1[2l][k], W1[2l+1][k])
    __shared__ float2 w2t[HID][HID / 2];   // w2t[i][l] = (W2[2l][i], W2[2l+1][i])
    __shared__ float  s2acc[TSTEP][HID];   // block-local spike sums
    __shared__ float  s3acc[TSTEP][ACT];

    const int tid = threadIdx.x;

    // --- stage weights (transposed) into shared ---
    for (int idx = tid; idx < SEQ * HID; idx += 256) {
        int k = idx / HID, j = idx % HID;
        ((float*)w1t)[k * HID + j] = W1[j * SEQ + k];
    }
    for (int idx = tid; idx < HID * HID; idx += 256) {
        int i = idx / HID, j = idx % HID;
        ((float*)w2t)[i * HID + j] = W2[j * HID + i];
    }
    for (int idx = tid; idx < TSTEP * HID; idx += 256)
        ((float*)s2acc)[idx] = 0.0f;
    if (tid < TSTEP * ACT)
        ((float*)s3acc)[tid] = 0.0f;
    __syncthreads();

    const int lane = tid & 31;
    const int warp = tid >> 5;
    const int j0 = 2 * lane, j1 = 2 * lane + 1;

    // per-lane constants
    const float b1_0 = b1[j0], b1_1 = b1[j1];
    const float b2_0 = b2[j0], b2_1 = b2[j1];
    float b3v0 = b3[0], b3v1 = b3[1], b3v2 = b3[2], b3v3 = b3[3];
    float w30_0 = W3[0 * HID + j0], w30_1 = W3[0 * HID + j1];
    float w31_0 = W3[1 * HID + j0], w31_1 = W3[1 * HID + j1];
    float w32_0 = W3[2 * HID + j0], w32_1 = W3[2 * HID + j1];
    float w33_0 = W3[3 * HID + j0], w33_1 = W3[3 * HID + j1];

    const int gwarp  = blockIdx.x * 8 + warp;
    const int nwarps = gridDim.x * 8;

    for (int row = gwarp; row < BSZ; row += nwarps) {
        // ---- cur1 = x[row] @ W1^T + b1  (identical every timestep) ----
        float cur0 = b1_0, cur1v = b1_1;
        const float* xr = x + row * SEQ;
        #pragma unroll
        for (int k = 0; k < SEQ; k++) {
            float xv = __ldg(xr + k);            // warp-broadcast load
            float2 w = w1t[k][lane];
            cur0  = fmaf(xv, w.x, cur0);
            cur1v = fmaf(xv, w.y, cur1v);
        }

        float m1_0 = 0.f, m1_1 = 0.f, m2_0 = 0.f, m2_1 = 0.f;
        float m3_0 = 0.f, m3_1 = 0.f, m3_2 = 0.f, m3_3 = 0.f;
        float ac0 = 0.f, ac1 = 0.f, ac2 = 0.f, ac3 = 0.f;

        for (int t = 0; t < TSTEP; t++) {
            // ---- layer 1 ----
            m1_0 = fmaf(BETA, m1_0, cur0);
            m1_1 = fmaf(BETA, m1_1, cur1v);
            bool f0 = m1_0 > THRV, f1 = m1_1 > THRV;
            if (f0) m1_0 -= THRV;
            if (f1) m1_1 -= THRV;
            unsigned ma = __ballot_sync(0xffffffffu, f0);  // bit l -> neuron 2l
            unsigned mb = __ballot_sync(0xffffffffu, f1);  // bit l -> neuron 2l+1

            // ---- layer 2 current: masked column sums of W2 (warp-uniform loops) ----
            float a0 = 0.f, a1 = 0.f;
            while (ma) {
                int i = __ffs(ma) - 1; ma &= ma - 1;
                float2 w = w2t[2 * i][lane];
                a0 += w.x; a1 += w.y;
            }
            while (mb) {
                int i = __ffs(mb) - 1; mb &= mb - 1;
                float2 w = w2t[2 * i + 1][lane];
                a0 += w.x; a1 += w.y;
            }
            m2_0 = fmaf(BETA, m2_0, a0 + b2_0);
            m2_1 = fmaf(BETA, m2_1, a1 + b2_1);
            float s2_0 = (m2_0 > THRV) ? 1.0f : 0.0f;
            float s2_1 = (m2_1 > THRV) ? 1.0f : 0.0f;
            m2_0 -= s2_0;   // THR = 1
            m2_1 -= s2_1;

            // block-level spike-sum accumulation (shared atomics, spread addrs)
            if (s2_0 != 0.0f) atomicAdd(&s2acc[t][j0], 1.0f);
            if (s2_1 != 0.0f) atomicAdd(&s2acc[t][j1], 1.0f);

            // ---- layer 3 current partials + butterfly reduce ----
            float p0 = fmaf(s2_0, w30_0, s2_1 * w30_1);
            float p1 = fmaf(s2_0, w31_0, s2_1 * w31_1);
            float p2 = fmaf(s2_0, w32_0, s2_1 * w32_1);
            float p3 = fmaf(s2_0, w33_0, s2_1 * w33_1);
            #pragma unroll
            for (int off = 16; off > 0; off >>= 1) {
                p0 += __shfl_xor_sync(0xffffffffu, p0, off);
                p1 += __shfl_xor_sync(0xffffffffu, p1, off);
                p2 += __shfl_xor_sync(0xffffffffu, p2, off);
                p3 += __shfl_xor_sync(0xffffffffu, p3, off);
            }

            m3_0 = fmaf(BETA, m3_0, p0 + b3v0);
            m3_1 = fmaf(BETA, m3_1, p1 + b3v1);
            m3_2 = fmaf(BETA, m3_2, p2 + b3v2);
            m3_3 = fmaf(BETA, m3_3, p3 + b3v3);
            float s3_0 = (m3_0 > THRV) ? 1.0f : 0.0f;
            float s3_1 = (m3_1 > THRV) ? 1.0f : 0.0f;
            float s3_2 = (m3_2 > THRV) ? 1.0f : 0.0f;
            float s3_3 = (m3_3 > THRV) ? 1.0f : 0.0f;
            m3_0 -= s3_0; m3_1 -= s3_1; m3_2 -= s3_2; m3_3 -= s3_3;
            ac0 += s3_0; ac1 += s3_1; ac2 += s3_2; ac3 += s3_3;

            if (lane == 0) {
                if (s3_0 != 0.f) atomicAdd(&s3acc[t][0], 1.0f);
                if (s3_1 != 0.f) atomicAdd(&s3acc[t][1], 1.0f);
                if (s3_2 != 0.f) atomicAdd(&s3acc[t][2], 1.0f);
                if (s3_3 != 0.f) atomicAdd(&s3acc[t][3], 1.0f);
            }
        }

        // ---- softmax(acc / T) ----
        const float invT = 1.0f / (float)TSTEP;
        float r0 = ac0 * invT, r1 = ac1 * invT, r2 = ac2 * invT, r3 = ac3 * invT;
        float mx = fmaxf(fmaxf(r0, r1), fmaxf(r2, r3));
        float e0 = expf(r0 - mx), e1 = expf(r1 - mx);
        float e2 = expf(r2 - mx), e3 = expf(r3 - mx);
        float s = e0 + e1 + e2 + e3;
        if (lane == 0) {
            float4 o = make_float4(e0 / s, e1 / s, e2 / s, e3 / s);
            *reinterpret_cast<float4*>(out + (size_t)row * ACT) = o;  // 16B aligned
        }
    }

    // ---- flush block-local spike sums to global ----
    __syncthreads();
    for (int idx = tid; idx < TSTEP * HID; idx += 256)
        atomicAdd(&g_s2sum[idx], ((float*)s2acc)[idx]);
    if (tid < TSTEP * ACT)
        atomicAdd(&g_s3sum[tid], ((float*)s3acc)[tid]);
}

// ---------------------------------------------------------------------------
// Kernel 2: eligibility trace. 256 threads, one per (a, h) pair.
// elig_t = 0.95*elig_{t-1} + c * post_t[a] * pre_t[h],  pre/post = spike means
// ---------------------------------------------------------------------------
__global__ void snn_elig(const float* __restrict__ elig0,
                         float* __restrict__ out, int elig_off) {
    int tid = threadIdx.x;                 // 256 = 4*64
    int a = tid >> 6;                      // 0..3
    int h = tid & 63;                      // 0..63
    const float invB = 1.0f / (float)BSZ;  // exact power of 2
    float e = elig0[tid];
    #pragma unroll
    for (int t = 0; t < TSTEP; t++) {
        float post = g_s3sum[t * ACT + a] * invB;
        float pre  = g_s2sum[t * HID + h] * invB;
        e = ELIG_DECAY * e + ELIG_C * (post * pre);
    }
    out[elig_off + tid] = e;
}

// ---------------------------------------------------------------------------
// Inputs (metadata order): x, W1, b1, W2, b2, W3, b3, elig0
// Output: probs [B,4] then elig [4,64] (elig placed at tail of out buffer)
// ---------------------------------------------------------------------------
extern "C" void kernel_launch(void* const* d_in, const int* in_sizes, int n_in,
                              void* d_out, int out_size) {
    const float* x     = (const float*)d_in[0];
    const float* W1    = (const float*)d_in[1];
    const float* b1    = (const float*)d_in[2];
    const float* W2    = (const float*)d_in[3];
    const float* b2    = (const float*)d_in[4];
    const float* W3    = (const float*)d_in[5];
    const float* b3    = (const float*)d_in[6];
    const float* elig0 = (const float*)d_in[7];
    float* out = (float*)d_out;

    snn_zero_sums<<<1, 1024>>>();
    snn_main<<<1024, 256>>>(x, W1, b1, W2, b2, W3, b3, out);
    int elig_off = out_size - ACT * HID;   // elig sits at the tail
    snn_elig<<<1, 256>>>(elig0, out, elig_off);
}

// round 4
// speedup vs baseline: 1.3919x; 1.3919x over previous
#include <cuda_runtime.h>
#include <math.h>

#define BSZ   65536
#define SEQ   25
#define HID   64
#define ACT   4
#define TSTEP 16
#define BETA  0.95f
#define THRV  1.0f
#define ELIG_DECAY 0.95f
#define ELIG_C     (-0.002f)   // A_PLUS - A_MINUS

#define NBLK   592              // 4 blocks x 148 SMs, single wave
// 65536 = 4736*13 + 3968 -> first 3968 warps take 14 rows, rest 13 (max 14 <= nibble cap 15)
#define ROWS_EXTRA 3968

#define W3_SCALE     8388608.0f          // 2^23
#define W3_INV_SCALE (1.0f / 8388608.0f)

// Global scratch (graph-safe __device__ globals, zero-initialized at load;
// snn_elig re-zeroes them after consuming, so every kernel_launch call sees zeros)
__device__ float g_s2sum[TSTEP * HID];
__device__ float g_s3sum[TSTEP * ACT];

__device__ __forceinline__ int warp_redux_add_s32(int v) {
    int r;
    asm volatile("redux.sync.add.s32 %0, %1, 0xffffffff;" : "=r"(r) : "r"(v));
    return r;
}

// ---------------------------------------------------------------------------
// Main SNN kernel. One warp per batch row (13-14 rows per warp).
// Lane l owns hidden neurons j0=2l, j1=2l+1 for layers 1 and 2.
// Layer 3 (A=4) via exact integer warp reduction (redux.sync.add.s32),
// result replicated to all lanes.
// ---------------------------------------------------------------------------
__global__ void __launch_bounds__(256, 4) snn_main(
    const float* __restrict__ x,   // [B, 25]
    const float* __restrict__ W1,  // [64, 25]
    const float* __restrict__ b1,  // [64]
    const float* __restrict__ W2,  // [64, 64]
    const float* __restrict__ b2,  // [64]
    const float* __restrict__ W3,  // [4, 64]
    const float* __restrict__ b3,  // [4]
    float* __restrict__ out)       // probs at [0, B*4)
{
    __shared__ float2   w1t[SEQ][HID / 2];   // w1t[k][l] = (W1[2l][k], W1[2l+1][k])
    __shared__ float2   w2t[HID][HID / 2];   // w2t[c][l] = (W2[2l][c], W2[2l+1][c])
    __shared__ unsigned s2sh[8][32][4];      // per-warp packed s2 counters
    __shared__ unsigned s3sh[8][32][2];      // per-warp distributed s3 counters

    const int tid = threadIdx.x;

    // stage transposed weights
    for (int idx = tid; idx < SEQ * HID; idx += 256) {
        int k = idx / HID, j = idx % HID;
        ((float*)w1t)[k * HID + j] = W1[j * SEQ + k];
    }
    for (int idx = tid; idx < HID * HID; idx += 256) {
        int c = idx / HID, j = idx % HID;
        ((float*)w2t)[c * HID + j] = W2[j * HID + c];
    }
    __syncthreads();

    const int lane = tid & 31;
    const int warp = tid >> 5;
    const int j0 = 2 * lane, j1 = 2 * lane + 1;
    const int lmod = lane & 15;
    const int lhi  = lane >> 4;    // 0/1

    // per-lane constants
    const float b2_0 = b2[j0], b2_1 = b2[j1];
    const float b3v0 = b3[0], b3v1 = b3[1], b3v2 = b3[2], b3v3 = b3[3];
    const float b1_0 = b1[j0], b1_1 = b1[j1];

    // quantized W3 (exact integer reduction; |w|<=0.125 -> |wq|<=2^20, 64-sum < 2^26)
    const int w30q0 = __float2int_rn(W3[0 * HID + j0] * W3_SCALE);
    const int w30q1 = __float2int_rn(W3[0 * HID + j1] * W3_SCALE);
    const int w31q0 = __float2int_rn(W3[1 * HID + j0] * W3_SCALE);
    const int w31q1 = __float2int_rn(W3[1 * HID + j1] * W3_SCALE);
    const int w32q0 = __float2int_rn(W3[2 * HID + j0] * W3_SCALE);
    const int w32q1 = __float2int_rn(W3[2 * HID + j1] * W3_SCALE);
    const int w33q0 = __float2int_rn(W3[3 * HID + j0] * W3_SCALE);
    const int w33q1 = __float2int_rn(W3[3 * HID + j1] * W3_SCALE);

    // shared base addresses for raw LDS
    const unsigned w2base =
        (unsigned)__cvta_generic_to_shared(&w2t[0][0]) + (unsigned)lane * 8u;

    // packed b2 pair for a01 init
    unsigned long long b2p;
    asm("mov.b64 %0, {%1, %2};" : "=l"(b2p) : "f"(b2_0), "f"(b2_1));

    // spike counters (accumulated over this warp's rows, <= 14 each)
    unsigned c0[2] = {0u, 0u};   // neuron j0: [t<8], [t>=8], nibble per t
    unsigned c1[2] = {0u, 0u};   // neuron j1
    unsigned cA = 0u, cB = 0u;   // s3: (t=lmod, a=lhi) and (t=lmod, a=2+lhi)

    const int gwarp = blockIdx.x * 8 + warp;
    const int row0  = gwarp * 13 + min(gwarp, ROWS_EXTRA);
    const int nrows = 13 + (gwarp < ROWS_EXTRA ? 1 : 0);

    for (int r = 0; r < nrows; r++) {
        const int row = row0 + r;

        // cur1 = x[row] @ W1^T + b1 (same every timestep)
        float cur0 = b1_0, cur1v = b1_1;
        const float* xr = x + row * SEQ;
        #pragma unroll
        for (int k = 0; k < SEQ; k++) {
            float xv = __ldg(xr + k);       // warp-uniform broadcast
            float2 w = w1t[k][lane];
            cur0  = fmaf(xv, w.x, cur0);
            cur1v = fmaf(xv, w.y, cur1v);
        }

        float m1_0 = 0.f, m1_1 = 0.f, m2_0 = 0.f, m2_1 = 0.f;
        float m3_0 = 0.f, m3_1 = 0.f, m3_2 = 0.f, m3_3 = 0.f;
        float ac0 = 0.f, ac1 = 0.f, ac2 = 0.f, ac3 = 0.f;

        #pragma unroll
        for (int th = 0; th < 2; th++) {
            const int lrel = lmod - th * 8;
            for (int tt = 0; tt < 8; tt++) {
                // ---- layer 1 ----
                m1_0 = fmaf(BETA, m1_0, cur0);
                m1_1 = fmaf(BETA, m1_1, cur1v);
                bool f0 = m1_0 > THRV, f1 = m1_1 > THRV;
                if (f0) m1_0 -= THRV;
                if (f1) m1_1 -= THRV;
                unsigned ma = __ballot_sync(0xffffffffu, f0);  // bit l -> neuron 2l
                unsigned mb = __ballot_sync(0xffffffffu, f1);  // bit l -> neuron 2l+1

                // ---- layer 2 current: masked W2 column sums (warp-uniform) ----
                unsigned long long a01 = b2p;
                while (ma) {
                    int i = __ffs(ma) - 1; ma &= ma - 1;
                    unsigned addr = w2base + ((unsigned)i << 9);      // col 2i
                    unsigned long long w;
                    asm volatile("ld.shared.b64 %0, [%1];" : "=l"(w) : "r"(addr));
                    asm volatile("add.rn.f32x2 %0, %0, %1;" : "+l"(a01) : "l"(w));
                }
                while (mb) {
                    int i = __ffs(mb) - 1; mb &= mb - 1;
                    unsigned addr = w2base + ((unsigned)i << 9) + 256u; // col 2i+1
                    unsigned long long w;
                    asm volatile("ld.shared.b64 %0, [%1];" : "=l"(w) : "r"(addr));
                    asm volatile("add.rn.f32x2 %0, %0, %1;" : "+l"(a01) : "l"(w));
                }
                float a0, a1;
                asm("mov.b64 {%0, %1}, %2;" : "=f"(a0), "=f"(a1) : "l"(a01));

                m2_0 = fmaf(BETA, m2_0, a0);
                m2_1 = fmaf(BETA, m2_1, a1);
                bool q0 = m2_0 > THRV, q1 = m2_1 > THRV;
                if (q0) m2_0 -= THRV;
                if (q1) m2_1 -= THRV;

                // s2 counters (registers, nibble per timestep)
                unsigned nib = 1u << (tt * 4);
                c0[th] += q0 ? nib : 0u;
                c1[th] += q1 ? nib : 0u;

                // ---- layer 3: exact integer partial + warp redux ----
                int p0i = (q0 ? w30q0 : 0) + (q1 ? w30q1 : 0);
                int p1i = (q0 ? w31q0 : 0) + (q1 ? w31q1 : 0);
                int p2i = (q0 ? w32q0 : 0) + (q1 ? w32q1 : 0);
                int p3i = (q0 ? w33q0 : 0) + (q1 ? w33q1 : 0);
                p0i = warp_redux_add_s32(p0i);
                p1i = warp_redux_add_s32(p1i);
                p2i = warp_redux_add_s32(p2i);
                p3i = warp_redux_add_s32(p3i);
                float p0 = fmaf((float)p0i, W3_INV_SCALE, b3v0);
                float p1 = fmaf((float)p1i, W3_INV_SCALE, b3v1);
                float p2 = fmaf((float)p2i, W3_INV_SCALE, b3v2);
                float p3 = fmaf((float)p3i, W3_INV_SCALE, b3v3);

                m3_0 = fmaf(BETA, m3_0, p0);
                m3_1 = fmaf(BETA, m3_1, p1);
                m3_2 = fmaf(BETA, m3_2, p2);
                m3_3 = fmaf(BETA, m3_3, p3);
                bool g0 = m3_0 > THRV, g1 = m3_1 > THRV;
                bool g2 = m3_2 > THRV, g3 = m3_3 > THRV;
                if (g0) { m3_0 -= THRV; ac0 += 1.0f; }
                if (g1) { m3_1 -= THRV; ac1 += 1.0f; }
                if (g2) { m3_2 -= THRV; ac2 += 1.0f; }
                if (g3) { m3_3 -= THRV; ac3 += 1.0f; }

                // s3 counters: this lane owns (t=lmod, a=lhi) and (t=lmod, a=2+lhi)
                int selA = lhi ? (g1 ? 1 : 0) : (g0 ? 1 : 0);
                int selB = lhi ? (g3 ? 1 : 0) : (g2 ? 1 : 0);
                bool on = (lrel == tt);
                cA += on ? (unsigned)selA : 0u;
                cB += on ? (unsigned)selB : 0u;
            }
        }

        // ---- output: softmax(acc / T) ----
        if (lane == 0) {
            const float invT = 1.0f / (float)TSTEP;
            float r0 = ac0 * invT, r1 = ac1 * invT, r2 = ac2 * invT, r3 = ac3 * invT;
            float mx = fmaxf(fmaxf(r0, r1), fmaxf(r2, r3));
            float e0 = __expf(r0 - mx), e1 = __expf(r1 - mx);
            float e2 = __expf(r2 - mx), e3 = __expf(r3 - mx);
            float rs = __fdividef(1.0f, e0 + e1 + e2 + e3);
            float4 o = make_float4(e0 * rs, e1 * rs, e2 * rs, e3 * rs);
            *reinterpret_cast<float4*>(out + (size_t)row * ACT) = o;
        }
    }

    // ---- flush spike counters: block reduce in shared, one global sweep ----
    s2sh[warp][lane][0] = c0[0];
    s2sh[warp][lane][1] = c0[1];
    s2sh[warp][lane][2] = c1[0];
    s2sh[warp][lane][3] = c1[1];
    s3sh[warp][lane][0] = cA;
    s3sh[warp][lane][1] = cB;
    __syncthreads();

    for (int p = tid; p < TSTEP * HID; p += 256) {
        int t = p >> 6, j = p & 63;
        int ln = j >> 1, od = j & 1;
        int wsel = od * 2 + (t >> 3);
        int sh = (t & 7) * 4;
        unsigned c = 0;
        #pragma unroll
        for (int w = 0; w < 8; w++)
            c += (s2sh[w][ln][wsel] >> sh) & 15u;
        atomicAdd(&g_s2sum[p], (float)c);
    }
    if (tid < TSTEP * ACT) {
        int t = tid >> 2, a = tid & 3;
        int ln = t + ((a & 1) << 4);
        int s = a >> 1;
        unsigned c = 0;
        #pragma unroll
        for (int w = 0; w < 8; w++)
            c += s3sh[w][ln][s];
        atomicAdd(&g_s3sum[tid], (float)c);
    }
}

// ---------------------------------------------------------------------------
// Eligibility trace + reset of global accumulators (single block).
// ---------------------------------------------------------------------------
__global__ void snn_elig(const float* __restrict__ elig0,
                         float* __restrict__ out, int elig_off) {
    int tid = threadIdx.x;                 // 256 = 4*64
    int a = tid >> 6;                      // 0..3
    int h = tid & 63;                      // 0..63
    const float invB = 1.0f / (float)BSZ;  // exact power of 2
    float e = elig0[tid];
    #pragma unroll
    for (int t = 0; t < TSTEP; t++) {
        float post = g_s3sum[t * ACT + a] * invB;
        float pre  = g_s2sum[t * HID + h] * invB;
        e = ELIG_DECAY * e + ELIG_C * (post * pre);
    }
    out[elig_off + tid] = e;

    // re-zero accumulators for the next invocation (graph replay safe)
    __syncthreads();
    for (int i = tid; i < TSTEP * HID; i += 256) g_s2sum[i] = 0.0f;
    if (tid < TSTEP * ACT) g_s3sum[tid] = 0.0f;
}

// ---------------------------------------------------------------------------
// Inputs (metadata order): x, W1, b1, W2, b2, W3, b3, elig0
// Output: probs [B,4] then elig [4,64] at the tail of out.
// ---------------------------------------------------------------------------
extern "C" void kernel_launch(void* const* d_in, const int* in_sizes, int n_in,
                              void* d_out, int out_size) {
    const float* x     = (const float*)d_in[0];
    const float* W1    = (const float*)d_in[1];
    const float* b1    = (const float*)d_in[2];
    const float* W2    = (const float*)d_in[3];
    const float* b2    = (const float*)d_in[4];
    const float* W3    = (const float*)d_in[5];
    const float* b3    = (const float*)d_in[6];
    const float* elig0 = (const float*)d_in[7];
    float* out = (float*)d_out;

    snn_main<<<NBLK, 256>>>(x, W1, b1, W2, b2, W3, b3, out);
    int elig_off = out_size - ACT * HID;
    snn_elig<<<1, 256>>>(elig0, out, elig_off);
}

// round 5
// speedup vs baseline: 1.9487x; 1.4000x over previous
#include <cuda_runtime.h>
#include <math.h>

#define BSZ   65536
#define SEQ   25
#define HID   64
#define ACT   4
#define TSTEP 16
#define BETA  0.95f
#define THRV  1.0f
#define ELIG_DECAY 0.95f
#define ELIG_C     (-0.002f)    // A_PLUS - A_MINUS

#define NBLK  296               // 2 blocks x 148 SMs, single wave
#define WPB   16                // warps per block (512 threads)
#define NWARP (NBLK * WPB)      // 4736
// 65536 = 4736*13 + 3968 -> first 3968 warps take 14 rows (<= nibble cap 15)
#define ROWS_EXTRA 3968

#define W3_SCALE     8388608.0f          // 2^23 (exact integer reduction)
#define W3_INV_SCALE (1.0f / 8388608.0f)

// Graph-safe persistent scratch; the last block re-zeroes everything each call.
__device__ float    g_s2sum[TSTEP * HID];
__device__ float    g_s3sum[TSTEP * ACT];
__device__ unsigned g_ctr;

struct Smem {
    float2   tbl[16][16][32];     // [group][pattern][lane] partial W2-col sums (64KB)
    float2   w1t[SEQ][32];        // w1t[k][l] = (W1[l][k], W1[l+32][k])
    unsigned s2sh[WPB][32][4];    // per-warp packed s2 counters
    unsigned s3sh[WPB][32][2];    // per-warp distributed s3 counters
    unsigned last_flag;
};

__device__ __forceinline__ int warp_redux_add_s32(int v) {
    int r;
    asm volatile("redux.sync.add.s32 %0, %1, 0xffffffff;" : "=r"(r) : "r"(v));
    return r;
}

// One LUT lookup: group G (0..15), pattern from 4-bit slice of mask.
template <int G>
__device__ __forceinline__ void lut_acc(unsigned mask, unsigned tb,
                                        unsigned long long& acc) {
    unsigned pat = (mask >> (4 * (G & 7))) & 15u;
    unsigned addr = tb + (pat << 8);
    unsigned long long w;
    asm volatile("ld.shared.b64 %0, [%1+%2];"
                 : "=l"(w) : "r"(addr), "n"(G * 4096));
    asm volatile("add.rn.f32x2 %0, %0, %1;" : "+l"(acc) : "l"(w));
}

// ---------------------------------------------------------------------------
// Single fused kernel. One warp per batch row (13-14 rows per warp).
// Lane l owns hidden neurons l and l+32 (layers 1, 2).
// ---------------------------------------------------------------------------
__global__ void __launch_bounds__(512, 2) snn_main(
    const float* __restrict__ x,   // [B, 25]
    const float* __restrict__ W1,  // [64, 25]
    const float* __restrict__ b1,  // [64]
    const float* __restrict__ W2,  // [64, 64]
    const float* __restrict__ b2,  // [64]
    const float* __restrict__ W3,  // [4, 64]
    const float* __restrict__ b3,  // [4]
    const float* __restrict__ elig0,
    float* __restrict__ out, int elig_off)
{
    extern __shared__ unsigned char smem_raw[];
    Smem* sm = reinterpret_cast<Smem*>(smem_raw);

    const int tid  = threadIdx.x;
    const int lane = tid & 31;
    const int warp = tid >> 5;

    // ---- build the 4-bit-group LUT: thread (g=warp, l=lane) owns 16 entries ----
    {
        const int g = warp;                       // 0..15
        const int l = lane;
        const int ibase = (g & 7) * 4 + (g >> 3) * 32;
        float2 c[4];
        #pragma unroll
        for (int b = 0; b < 4; b++) {
            int i = ibase + b;
            c[b].x = W2[l * HID + i];
            c[b].y = W2[(l + 32) * HID + i];
        }
        float2 e[16];
        e[0] = make_float2(0.f, 0.f);
        #pragma unroll
        for (int p = 1; p < 16; p++) {
            int lb = p & (-p);
            int bi = (lb == 1) ? 0 : (lb == 2) ? 1 : (lb == 4) ? 2 : 3;
            e[p].x = e[p ^ lb].x + c[bi].x;
            e[p].y = e[p ^ lb].y + c[bi].y;
        }
        #pragma unroll
        for (int p = 0; p < 16; p++) sm->tbl[g][p][l] = e[p];
    }
    // ---- stage W1 transposed ----
    for (int idx = tid; idx < SEQ * 32; idx += 512) {
        int k = idx >> 5, l = idx & 31;
        sm->w1t[k][l] = make_float2(W1[l * SEQ + k], W1[(l + 32) * SEQ + k]);
    }
    __syncthreads();

    // per-lane constants (neurons l and l+32)
    const float b1_0 = b1[lane],       b1_1 = b1[lane + 32];
    const float b2_0 = b2[lane],       b2_1 = b2[lane + 32];
    const float b3v0 = b3[0], b3v1 = b3[1], b3v2 = b3[2], b3v3 = b3[3];
    const int w30q0 = __float2int_rn(W3[0 * HID + lane]      * W3_SCALE);
    const int w30q1 = __float2int_rn(W3[0 * HID + lane + 32] * W3_SCALE);
    const int w31q0 = __float2int_rn(W3[1 * HID + lane]      * W3_SCALE);
    const int w31q1 = __float2int_rn(W3[1 * HID + lane + 32] * W3_SCALE);
    const int w32q0 = __float2int_rn(W3[2 * HID + lane]      * W3_SCALE);
    const int w32q1 = __float2int_rn(W3[2 * HID + lane + 32] * W3_SCALE);
    const int w33q0 = __float2int_rn(W3[3 * HID + lane]      * W3_SCALE);
    const int w33q1 = __float2int_rn(W3[3 * HID + lane + 32] * W3_SCALE);

    const unsigned tb =
        (unsigned)__cvta_generic_to_shared(&sm->tbl[0][0][0]) + (unsigned)lane * 8u;

    unsigned long long b2p;
    asm("mov.b64 %0, {%1, %2};" : "=l"(b2p) : "f"(b2_0), "f"(b2_1));

    const int lmod = lane & 15;
    const int lhi  = lane >> 4;

    // spike counters (per-warp, register-resident; max 14 per nibble)
    unsigned c0[2] = {0u, 0u};   // neuron l
    unsigned c1[2] = {0u, 0u};   // neuron l+32
    unsigned cA = 0u, cB = 0u;   // s3 at (t=lmod, a=lhi) and (t=lmod, a=2+lhi)

    const int gwarp = blockIdx.x * WPB + warp;
    const int row0  = gwarp * 13 + min(gwarp, ROWS_EXTRA);
    const int nrows = 13 + (gwarp < ROWS_EXTRA ? 1 : 0);

    for (int r = 0; r < nrows; r++) {
        const int row = row0 + r;

        // ---- cur1 = x[row] @ W1^T + b1 (coalesced load + shfl broadcast) ----
        const float* xr = x + row * SEQ;
        float xown = (lane < SEQ) ? xr[lane] : 0.0f;
        float cur0 = b1_0, cur1v = b1_1;
        #pragma unroll
        for (int k = 0; k < SEQ; k++) {
            float xv = __shfl_sync(0xffffffffu, xown, k);
            float2 w = sm->w1t[k][lane];
            cur0  = fmaf(xv, w.x, cur0);
            cur1v = fmaf(xv, w.y, cur1v);
        }

        float m1_0 = 0.f, m1_1 = 0.f, m2_0 = 0.f, m2_1 = 0.f;
        float m3_0 = 0.f, m3_1 = 0.f, m3_2 = 0.f, m3_3 = 0.f;
        float ac0 = 0.f, ac1 = 0.f, ac2 = 0.f, ac3 = 0.f;

        #pragma unroll
        for (int th = 0; th < 2; th++) {
            const int lrel = lmod - th * 8;
            #pragma unroll 1
            for (int tt = 0; tt < 8; tt++) {
                // ---- layer 1 ----
                m1_0 = fmaf(BETA, m1_0, cur0);
                m1_1 = fmaf(BETA, m1_1, cur1v);
                bool f0 = m1_0 > THRV, f1 = m1_1 > THRV;
                if (f0) m1_0 -= THRV;
                if (f1) m1_1 -= THRV;
                unsigned ma = __ballot_sync(0xffffffffu, f0);  // neurons 0..31
                unsigned mb = __ballot_sync(0xffffffffu, f1);  // neurons 32..63

                // ---- layer 2: 16 branch-free LUT lookups, 4 accumulators ----
                unsigned long long a01 = b2p, aA = 0, aB = 0, aC = 0;
                lut_acc< 0>(ma, tb, a01); lut_acc< 1>(ma, tb, aA);
                lut_acc< 2>(ma, tb, aB);  lut_acc< 3>(ma, tb, aC);
                lut_acc< 4>(ma, tb, a01); lut_acc< 5>(ma, tb, aA);
                lut_acc< 6>(ma, tb, aB);  lut_acc< 7>(ma, tb, aC);
                lut_acc< 8>(mb, tb, a01); lut_acc< 9>(mb, tb, aA);
                lut_acc<10>(mb, tb, aB);  lut_acc<11>(mb, tb, aC);
                lut_acc<12>(mb, tb, a01); lut_acc<13>(mb, tb, aA);
                lut_acc<14>(mb, tb, aB);  lut_acc<15>(mb, tb, aC);
                asm("add.rn.f32x2 %0, %0, %1;" : "+l"(a01) : "l"(aA));
                asm("add.rn.f32x2 %0, %0, %1;" : "+l"(aB)  : "l"(aC));
                asm("add.rn.f32x2 %0, %0, %1;" : "+l"(a01) : "l"(aB));
                float a0, a1;
                asm("mov.b64 {%0, %1}, %2;" : "=f"(a0), "=f"(a1) : "l"(a01));

                m2_0 = fmaf(BETA, m2_0, a0);
                m2_1 = fmaf(BETA, m2_1, a1);
                bool q0 = m2_0 > THRV, q1 = m2_1 > THRV;
                if (q0) m2_0 -= THRV;
                if (q1) m2_1 -= THRV;

                unsigned nib = 1u << (tt * 4);
                c0[th] += q0 ? nib : 0u;
                c1[th] += q1 ? nib : 0u;

                // ---- layer 3: exact integer partials + warp redux ----
                int p0i = (q0 ? w30q0 : 0) + (q1 ? w30q1 : 0);
                int p1i = (q0 ? w31q0 : 0) + (q1 ? w31q1 : 0);
                int p2i = (q0 ? w32q0 : 0) + (q1 ? w32q1 : 0);
                int p3i = (q0 ? w33q0 : 0) + (q1 ? w33q1 : 0);
                p0i = warp_redux_add_s32(p0i);
                p1i = warp_redux_add_s32(p1i);
                p2i = warp_redux_add_s32(p2i);
                p3i = warp_redux_add_s32(p3i);
                float p0 = fmaf((float)p0i, W3_INV_SCALE, b3v0);
                float p1 = fmaf((float)p1i, W3_INV_SCALE, b3v1);
                float p2 = fmaf((float)p2i, W3_INV_SCALE, b3v2);
                float p3 = fmaf((float)p3i, W3_INV_SCALE, b3v3);

                m3_0 = fmaf(BETA, m3_0, p0);
                m3_1 = fmaf(BETA, m3_1, p1);
                m3_2 = fmaf(BETA, m3_2, p2);
                m3_3 = fmaf(BETA, m3_3, p3);
                bool g0 = m3_0 > THRV, g1 = m3_1 > THRV;
                bool g2 = m3_2 > THRV, g3 = m3_3 > THRV;
                if (g0) { m3_0 -= THRV; ac0 += 1.0f; }
                if (g1) { m3_1 -= THRV; ac1 += 1.0f; }
                if (g2) { m3_2 -= THRV; ac2 += 1.0f; }
                if (g3) { m3_3 -= THRV; ac3 += 1.0f; }

                int selA = lhi ? (g1 ? 1 : 0) : (g0 ? 1 : 0);
                int selB = lhi ? (g3 ? 1 : 0) : (g2 ? 1 : 0);
                bool on = (lrel == tt);
                cA += on ? (unsigned)selA : 0u;
                cB += on ? (unsigned)selB : 0u;
            }
        }

        // ---- softmax(acc / T) ----
        if (lane == 0) {
            const float invT = 1.0f / (float)TSTEP;
            float r0 = ac0 * invT, r1 = ac1 * invT, r2 = ac2 * invT, r3 = ac3 * invT;
            float mx = fmaxf(fmaxf(r0, r1), fmaxf(r2, r3));
            float e0 = __expf(r0 - mx), e1 = __expf(r1 - mx);
            float e2 = __expf(r2 - mx), e3 = __expf(r3 - mx);
            float rs = __fdividef(1.0f, e0 + e1 + e2 + e3);
            float4 o = make_float4(e0 * rs, e1 * rs, e2 * rs, e3 * rs);
            *reinterpret_cast<float4*>(out + (size_t)row * ACT) = o;
        }
    }

    // ---- flush spike counters: block reduce in shared, one global sweep ----
    sm->s2sh[warp][lane][0] = c0[0];
    sm->s2sh[warp][lane][1] = c0[1];
    sm->s2sh[warp][lane][2] = c1[0];
    sm->s2sh[warp][lane][3] = c1[1];
    sm->s3sh[warp][lane][0] = cA;
    sm->s3sh[warp][lane][1] = cB;
    __syncthreads();

    for (int p = tid; p < TSTEP * HID; p += 512) {
        int t = p >> 6, j = p & 63;
        int ln = j & 31, half = j >> 5;
        int wsel = half * 2 + (t >> 3);
        int sh = (t & 7) * 4;
        unsigned c = 0;
        #pragma unroll
        for (int w = 0; w < WPB; w++)
            c += (sm->s2sh[w][ln][wsel] >> sh) & 15u;
        atomicAdd(&g_s2sum[p], (float)c);
    }
    if (tid < TSTEP * ACT) {
        int t = tid >> 2, a = tid & 3;
        int ln = t + ((a & 1) << 4);
        int s = a >> 1;
        unsigned c = 0;
        #pragma unroll
        for (int w = 0; w < WPB; w++)
            c += sm->s3sh[w][ln][s];
        atomicAdd(&g_s3sum[tid], (float)c);
    }

    // ---- last-block: eligibility trace + reset of globals ----
    __threadfence();
    __syncthreads();
    if (tid == 0)
        sm->last_flag = (atomicAdd(&g_ctr, 1u) == (unsigned)(NBLK - 1)) ? 1u : 0u;
    __syncthreads();
    if (sm->last_flag) {
        if (tid < ACT * HID) {
            int a = tid >> 6, h = tid & 63;
            const float invB = 1.0f / (float)BSZ;
            volatile float* s3v = g_s3sum;
            volatile float* s2v = g_s2sum;
            float e = elig0[tid];
            #pragma unroll
            for (int t = 0; t < TSTEP; t++) {
                float post = s3v[t * ACT + a] * invB;
                float pre  = s2v[t * HID + h] * invB;
                e = ELIG_DECAY * e + ELIG_C * (post * pre);
            }
            out[elig_off + tid] = e;
        }
        __syncthreads();
        for (int i = tid; i < TSTEP * HID; i += 512) g_s2sum[i] = 0.0f;
        if (tid < TSTEP * ACT) g_s3sum[tid] = 0.0f;
        if (tid == 0) g_ctr = 0u;
    }
}

// ---------------------------------------------------------------------------
// Inputs (metadata order): x, W1, b1, W2, b2, W3, b3, elig0
// Output: probs [B,4] then elig [4,64] at the tail of out.
// ---------------------------------------------------------------------------
extern "C" void kernel_launch(void* const* d_in, const int* in_sizes, int n_in,
                              void* d_out, int out_size) {
    const float* x     = (const float*)d_in[0];
    const float* W1    = (const float*)d_in[1];
    const float* b1    = (const float*)d_in[2];
    const float* W2    = (const float*)d_in[3];
    const float* b2    = (const float*)d_in[4];
    const float* W3    = (const float*)d_in[5];
    const float* b3    = (const float*)d_in[6];
    const float* elig0 = (const float*)d_in[7];
    float* out = (float*)d_out;

    int smem_bytes = (int)sizeof(Smem);
    cudaFuncSetAttribute(snn_main, cudaFuncAttributeMaxDynamicSharedMemorySize,
                         smem_bytes);
    int elig_off = out_size - ACT * HID;
    snn_main<<<NBLK, 512, smem_bytes>>>(x, W1, b1, W2, b2, W3, b3,
                                        elig0, out, elig_off);
}

// round 6
// speedup vs baseline: 2.7856x; 1.4294x over previous
#include <cuda_runtime.h>
#include <math.h>

#define BSZ   65536
#define SEQ   25
#define HID   64
#define ACT   4
#define TSTEP 16
#define BETA  0.95f
#define THRV  1.0f
#define ELIG_DECAY 0.95f
#define ELIG_C     (-0.002f)    // A_PLUS - A_MINUS

#define NBLK  148               // 1 block per SM, single wave
#define WPB   32                // warps per block (1024 threads)
// 65536 = 4736*13 + 3968 -> first 3968 warps take 14 rows (<= nibble cap 15)
#define ROWS_EXTRA 3968

#define W3_SCALE     8388608.0f          // 2^23 (exact integer reduction)
#define W3_INV_SCALE (1.0f / 8388608.0f)

// Graph-safe persistent scratch; last block re-zeroes everything each call.
__device__ float    g_s2sum[TSTEP * HID];
__device__ float    g_s3sum[TSTEP * ACT];
__device__ unsigned g_ctr;

// smem layout (offsets in bytes)
//   tbl6 : 10 groups x 64 patterns x 32 lanes x float2 = 163840
//   tbl4 :  1 group  x 16 patterns x 32 lanes x float2 =   4096
//   w1t  : 25 x 32 x float2                            =   6400
//   s2sh : 32 warps x 32 lanes x 4 u32                 =  16384
//   s3sh : 32 warps x 32 lanes x 2 u32                 =   8192
//   flag : 4
struct Smem {
    float2   tbl6[10][64][32];
    float2   tbl4[16][32];
    float2   w1t[SEQ][32];
    unsigned s2sh[WPB][32][4];
    unsigned s3sh[WPB][32][2];
    unsigned last_flag;
};
#define TBL4_OFF 163840          // byte offset of tbl4 from tbl6 base

__device__ __forceinline__ int warp_redux_add_s32(int v) {
    int r;
    asm volatile("redux.sync.add.s32 %0, %1, 0xffffffff;" : "=r"(r) : "r"(v));
    return r;
}

// 6-bit-group LUT lookup. X already shifted so pattern is in bits [0,6).
template <int IMM>
__device__ __forceinline__ void lut6(unsigned x, unsigned tb,
                                     unsigned long long& acc) {
    unsigned pat = x & 63u;
    unsigned addr = tb + pat * 256u;
    unsigned long long w;
    asm volatile("ld.shared.b64 %0, [%1+%2];" : "=l"(w) : "r"(addr), "n"(IMM));
    asm volatile("add.rn.f32x2 %0, %0, %1;" : "+l"(acc) : "l"(w));
}
__device__ __forceinline__ void lut4(unsigned x, unsigned tb,
                                     unsigned long long& acc) {
    unsigned pat = x & 15u;
    unsigned addr = tb + pat * 256u;
    unsigned long long w;
    asm volatile("ld.shared.b64 %0, [%1+%2];" : "=l"(w) : "r"(addr), "n"(TBL4_OFF));
    asm volatile("add.rn.f32x2 %0, %0, %1;" : "+l"(acc) : "l"(w));
}

// ---------------------------------------------------------------------------
// Fused kernel. One warp per batch row (13-14 rows/warp).
// Lane l owns hidden neurons l and l+32 (layers 1, 2).
// Layer 3: exact integer warp redux; lane l keeps m3/acc for action lane&3.
// ---------------------------------------------------------------------------
__global__ void __launch_bounds__(1024, 1) snn_main(
    const float* __restrict__ x,   // [B, 25]
    const float* __restrict__ W1,  // [64, 25]
    const float* __restrict__ b1,  // [64]
    const float* __restrict__ W2,  // [64, 64]
    const float* __restrict__ b2,  // [64]
    const float* __restrict__ W3,  // [4, 64]
    const float* __restrict__ b3,  // [4]
    const float* __restrict__ elig0,
    float* __restrict__ out, int elig_off)
{
    extern __shared__ unsigned char smem_raw[];
    Smem* sm = reinterpret_cast<Smem*>(smem_raw);

    const int tid  = threadIdx.x;
    const int lane = tid & 31;
    const int warp = tid >> 5;

    // ---- build 6-bit LUT: threads 0..319 -> (group, lane) chains ----
    if (tid < 320) {
        const int g = tid >> 5, l = tid & 31;
        float wa[6], wb[6];
        #pragma unroll
        for (int b = 0; b < 6; b++) {
            int j = 6 * g + b;
            wa[b] = W2[l * HID + j];
            wb[b] = W2[(l + 32) * HID + j];
        }
        sm->tbl6[g][0][l] = make_float2(0.f, 0.f);
        for (int n = 1; n < 64; n++) {
            int b = __ffs(n) - 1;
            float2 prev = sm->tbl6[g][n & (n - 1)][l];
            sm->tbl6[g][n][l] = make_float2(prev.x + wa[b], prev.y + wb[b]);
        }
    } else if (tid < 352) {
        const int l = tid - 320;
        float wa[4], wb[4];
        #pragma unroll
        for (int b = 0; b < 4; b++) {
            int j = 60 + b;
            wa[b] = W2[l * HID + j];
            wb[b] = W2[(l + 32) * HID + j];
        }
        sm->tbl4[0][l] = make_float2(0.f, 0.f);
        for (int n = 1; n < 16; n++) {
            int b = __ffs(n) - 1;
            float2 prev = sm->tbl4[n & (n - 1)][l];
            sm->tbl4[n][l] = make_float2(prev.x + wa[b], prev.y + wb[b]);
        }
    }
    // ---- stage W1 transposed ----
    for (int idx = tid; idx < SEQ * 32; idx += 1024) {
        int k = idx >> 5, l = idx & 31;
        sm->w1t[k][l] = make_float2(W1[l * SEQ + k], W1[(l + 32) * SEQ + k]);
    }
    __syncthreads();

    // per-lane constants
    const float b1_0 = b1[lane], b1_1 = b1[lane + 32];
    const float b2_0 = b2[lane], b2_1 = b2[lane + 32];
    const int   amine = lane & 3;          // action owned by this lane
    const float b3me  = b3[amine];
    const bool  lb0 = (lane & 1) != 0, lb1 = (lane & 2) != 0;
    const int w30q0 = __float2int_rn(W3[0 * HID + lane]      * W3_SCALE);
    const int w30q1 = __float2int_rn(W3[0 * HID + lane + 32] * W3_SCALE);
    const int w31q0 = __float2int_rn(W3[1 * HID + lane]      * W3_SCALE);
    const int w31q1 = __float2int_rn(W3[1 * HID + lane + 32] * W3_SCALE);
    const int w32q0 = __float2int_rn(W3[2 * HID + lane]      * W3_SCALE);
    const int w32q1 = __float2int_rn(W3[2 * HID + lane + 32] * W3_SCALE);
    const int w33q0 = __float2int_rn(W3[3 * HID + lane]      * W3_SCALE);
    const int w33q1 = __float2int_rn(W3[3 * HID + lane + 32] * W3_SCALE);

    const unsigned tb =
        (unsigned)__cvta_generic_to_shared(&sm->tbl6[0][0][0]) + (unsigned)lane * 8u;

    unsigned long long b2p;
    asm("mov.b64 %0, {%1, %2};" : "=l"(b2p) : "f"(b2_0), "f"(b2_1));

    const int lmod = lane & 15;
    const int lhi  = lane >> 4;

    // spike counters (register-resident; max 14 per nibble)
    unsigned c00 = 0u, c01 = 0u;   // neuron l: t 0-7, t 8-15
    unsigned c10 = 0u, c11 = 0u;   // neuron l+32
    unsigned cA = 0u, cB = 0u;     // s3 at (t=lmod, a=lhi) and (t=lmod, a=2+lhi)

    const int gwarp = blockIdx.x * WPB + warp;
    const int row0  = gwarp * 13 + min(gwarp, ROWS_EXTRA);
    const int nrows = 13 + (gwarp < ROWS_EXTRA ? 1 : 0);

    for (int r = 0; r < nrows; r++) {
        const int row = row0 + r;

        // ---- cur1 = x[row] @ W1^T + b1 (coalesced + shfl broadcast) ----
        const float* xr = x + row * SEQ;
        float xown = (lane < SEQ) ? xr[lane] : 0.0f;
        float cur0 = b1_0, cur1v = b1_1;
        #pragma unroll
        for (int k = 0; k < SEQ; k++) {
            float xv = __shfl_sync(0xffffffffu, xown, k);
            float2 w = sm->w1t[k][lane];
            cur0  = fmaf(xv, w.x, cur0);
            cur1v = fmaf(xv, w.y, cur1v);
        }

        float m1_0 = 0.f, m1_1 = 0.f, m2_0 = 0.f, m2_1 = 0.f;
        float m3me = 0.f, acme = 0.f;

        #pragma unroll
        for (int t = 0; t < TSTEP; t++) {
            // ---- layer 1 ----
            m1_0 = fmaf(BETA, m1_0, cur0);
            m1_1 = fmaf(BETA, m1_1, cur1v);
            bool f0 = m1_0 > THRV, f1 = m1_1 > THRV;
            if (f0) m1_0 -= THRV;
            if (f1) m1_1 -= THRV;
            unsigned ma = __ballot_sync(0xffffffffu, f0);  // neurons 0..31
            unsigned mb = __ballot_sync(0xffffffffu, f1);  // neurons 32..63

            // ---- layer 2: 11 branch-free LUT lookups, 4 accumulators ----
            unsigned long long a01 = b2p, aA = 0, aB = 0, aC = 0;
            lut6<0 * 16384>(ma,                             tb, a01);
            lut6<1 * 16384>(ma >> 6,                        tb, aA);
            lut6<2 * 16384>(ma >> 12,                       tb, aB);
            lut6<3 * 16384>(ma >> 18,                       tb, aC);
            lut6<4 * 16384>(ma >> 24,                       tb, a01);
            lut6<5 * 16384>(__funnelshift_r(ma, mb, 30),    tb, aA);
            lut6<6 * 16384>(mb >> 4,                        tb, aB);
            lut6<7 * 16384>(mb >> 10,                       tb, aC);
            lut6<8 * 16384>(mb >> 16,                       tb, a01);
            lut6<9 * 16384>(mb >> 22,                       tb, aA);
            lut4           (mb >> 28,                       tb, aB);
            asm("add.rn.f32x2 %0, %0, %1;" : "+l"(a01) : "l"(aA));
            asm("add.rn.f32x2 %0, %0, %1;" : "+l"(aB)  : "l"(aC));
            asm("add.rn.f32x2 %0, %0, %1;" : "+l"(a01) : "l"(aB));
            float a0, a1;
            asm("mov.b64 {%0, %1}, %2;" : "=f"(a0), "=f"(a1) : "l"(a01));

            m2_0 = fmaf(BETA, m2_0, a0);
            m2_1 = fmaf(BETA, m2_1, a1);
            bool q0 = m2_0 > THRV, q1 = m2_1 > THRV;
            if (q0) m2_0 -= THRV;
            if (q1) m2_1 -= THRV;

            // s2 nibble counters (t immediate under full unroll)
            unsigned nib = 1u << ((t & 7) * 4);
            if (t < 8) { c00 += q0 ? nib : 0u; c10 += q1 ? nib : 0u; }
            else       { c01 += q0 ? nib : 0u; c11 += q1 ? nib : 0u; }

            // ---- layer 3: exact integer partials + warp redux ----
            int s0i = q0 ? 1 : 0, s1i = q1 ? 1 : 0;
            int p0i = s0i * w30q0 + s1i * w30q1;
            int p1i = s0i * w31q0 + s1i * w31q1;
            int p2i = s0i * w32q0 + s1i * w32q1;
            int p3i = s0i * w33q0 + s1i * w33q1;
            p0i = warp_redux_add_s32(p0i);
            p1i = warp_redux_add_s32(p1i);
            p2i = warp_redux_add_s32(p2i);
            p3i = warp_redux_add_s32(p3i);

            // this lane updates only its own action
            int pm = lb1 ? (lb0 ? p3i : p2i) : (lb0 ? p1i : p0i);
            float pf = fmaf((float)pm, W3_INV_SCALE, b3me);
            m3me = fmaf(BETA, m3me, pf);
            bool gme = m3me > THRV;
            if (gme) { m3me -= THRV; acme += 1.0f; }

            // s3 counters via one ballot (bit a of bal = spike of action a)
            unsigned bal = __ballot_sync(0xffffffffu, gme);
            if (lmod == t) {
                cA += (bal >> lhi) & 1u;
                cB += (bal >> (2 + lhi)) & 1u;
            }
        }

        // ---- softmax(acc / T): gather 4 actions, lane 0 writes ----
        float g0 = __shfl_sync(0xffffffffu, acme, 0);
        float g1 = __shfl_sync(0xffffffffu, acme, 1);
        float g2 = __shfl_sync(0xffffffffu, acme, 2);
        float g3 = __shfl_sync(0xffffffffu, acme, 3);
        if (lane == 0) {
            const float invT = 1.0f / (float)TSTEP;
            float r0 = g0 * invT, r1 = g1 * invT, r2 = g2 * invT, r3 = g3 * invT;
            float mx = fmaxf(fmaxf(r0, r1), fmaxf(r2, r3));
            float e0 = __expf(r0 - mx), e1 = __expf(r1 - mx);
            float e2 = __expf(r2 - mx), e3 = __expf(r3 - mx);
            float rs = __fdividef(1.0f, e0 + e1 + e2 + e3);
            float4 o = make_float4(e0 * rs, e1 * rs, e2 * rs, e3 * rs);
            *reinterpret_cast<float4*>(out + (size_t)row * ACT) = o;
        }
    }

    // ---- flush spike counters: block reduce in shared, one global sweep ----
    sm->s2sh[warp][lane][0] = c00;
    sm->s2sh[warp][lane][1] = c01;
    sm->s2sh[warp][lane][2] = c10;
    sm->s2sh[warp][lane][3] = c11;
    sm->s3sh[warp][lane][0] = cA;
    sm->s3sh[warp][lane][1] = cB;
    __syncthreads();

    {   // 1024 (t, neuron) cells, one per thread
        int p = tid;
        int t = p >> 6, j = p & 63;
        int ln = j & 31, half = j >> 5;
        int wsel = half * 2 + (t >> 3);
        int sh = (t & 7) * 4;
        unsigned c = 0;
        #pragma unroll
        for (int w = 0; w < WPB; w++)
            c += (sm->s2sh[w][ln][wsel] >> sh) & 15u;
        atomicAdd(&g_s2sum[p], (float)c);
    }
    if (tid < TSTEP * ACT) {
        int t = tid >> 2, a = tid & 3;
        int ln = t + ((a & 1) << 4);
        int s = a >> 1;
        unsigned c = 0;
        #pragma unroll
        for (int w = 0; w < WPB; w++)
            c += sm->s3sh[w][ln][s];
        atomicAdd(&g_s3sum[tid], (float)c);
    }

    // ---- last-block: eligibility trace + reset of globals ----
    __threadfence();
    __syncthreads();
    if (tid == 0)
        sm->last_flag = (atomicAdd(&g_ctr, 1u) == (unsigned)(NBLK - 1)) ? 1u : 0u;
    __syncthreads();
    if (sm->last_flag) {
        if (tid < ACT * HID) {
            int a = tid >> 6, h = tid & 63;
            const float invB = 1.0f / (float)BSZ;
            volatile float* s3v = g_s3sum;
            volatile float* s2v = g_s2sum;
            float e = elig0[tid];
            #pragma unroll
            for (int t = 0; t < TSTEP; t++) {
                float post = s3v[t * ACT + a] * invB;
                float pre  = s2v[t * HID + h] * invB;
                e = ELIG_DECAY * e + ELIG_C * (post * pre);
            }
            out[elig_off + tid] = e;
        }
        __syncthreads();
        if (tid < TSTEP * HID) g_s2sum[tid] = 0.0f;
        if (tid < TSTEP * ACT) g_s3sum[tid] = 0.0f;
        if (tid == 0) g_ctr = 0u;
    }
}

// ---------------------------------------------------------------------------
// Inputs (metadata order): x, W1, b1, W2, b2, W3, b3, elig0
// Output: probs [B,4] then elig [4,64] at the tail of out.
// ---------------------------------------------------------------------------
extern "C" void kernel_launch(void* const* d_in, const int* in_sizes, int n_in,
                              void* d_out, int out_size) {
    const float* x     = (const float*)d_in[0];
    const float* W1    = (const float*)d_in[1];
    const float* b1    = (const float*)d_in[2];
    const float* W2    = (const float*)d_in[3];
    const float* b2    = (const float*)d_in[4];
    const float* W3    = (const float*)d_in[5];
    const float* b3    = (const float*)d_in[6];
    const float* elig0 = (const float*)d_in[7];
    float* out = (float*)d_out;

    int smem_bytes = (int)sizeof(Smem);
    cudaFuncSetAttribute(snn_main, cudaFuncAttributeMaxDynamicSharedMemorySize,
                         smem_bytes);
    int elig_off = out_size - ACT * HID;
    snn_main<<<NBLK, 1024, smem_bytes>>>(x, W1, b1, W2, b2, W3, b3,
                                         elig0, out, elig_off);
}